// round 3
// baseline (speedup 1.0000x reference)
#include <cuda_runtime.h>
#include <cstdint>

// Problem constants
#define BB     8192
#define TT     64
#define FF     64
#define ORD    16
#define KK     256          // hidden units
#define RTOT   336          // F + ORD + K  (inner GEMM dim)
#define KC     16           // k-chunk
#define MT     64           // rows per CTA
#define NT     64           // hidden units per CTA
#define NTHREADS 256

// ---------------- persistent device state (no allocations allowed) ----------
__device__ float  g_hbuf[2u * BB * KK];          // double-buffered h (16 MB)
__device__ float  g_c[BB * KK];                  // cell state (8 MB)
__device__ float  g_yp[BB * ORD];                // feedback window
__device__ float4 g_Wp[RTOT * KK];               // gate-interleaved weights
__device__ float4 g_biasp[KK];                   // gate-interleaved bias

// ---------------- packed fp32x2 helpers (Blackwell dual-fp32) ---------------
__device__ __forceinline__ void fma2(unsigned long long& d,
                                     unsigned long long a,
                                     unsigned long long b) {
    asm("fma.rn.f32x2 %0, %1, %2, %0;" : "+l"(d) : "l"(a), "l"(b));
}
__device__ __forceinline__ unsigned long long bcast2(float v) {
    unsigned long long r;
    asm("mov.b64 %0, {%1, %2};" : "=l"(r) : "f"(v), "f"(v));
    return r;
}
__device__ __forceinline__ float2 unpack2(unsigned long long v) {
    float2 r;
    asm("mov.b64 {%0, %1}, %2;" : "=f"(r.x), "=f"(r.y) : "l"(v));
    return r;
}

__device__ __forceinline__ float sigmoidf_(float x) {
    return 1.0f / (1.0f + expf(-x));
}

// ---------------- init: zero state, load feedback window --------------------
__global__ void init_kernel(const float* __restrict__ y0) {
    int i = blockIdx.x * blockDim.x + threadIdx.x;
    int stride = gridDim.x * blockDim.x;
    for (int s = i; s < 2 * BB * KK; s += stride) g_hbuf[s] = 0.0f;
    for (int s = i; s < BB * KK; s += stride)     g_c[s]   = 0.0f;
    for (int s = i; s < BB * ORD; s += stride)    g_yp[s]  = y0[s];
}

// ---------------- repack weights: Wp[r][n] = (i,f,g,o) gates ----------------
__global__ void repack_kernel(const float* __restrict__ kern,   // [80, 1024]
                              const float* __restrict__ rec,    // [256, 1024]
                              const float* __restrict__ bias) { // [1024]
    int i = blockIdx.x * blockDim.x + threadIdx.x;
    int stride = gridDim.x * blockDim.x;
    for (int idx = i; idx < RTOT * KK; idx += stride) {
        int r = idx / KK;
        int n = idx - r * KK;
        float4 w;
        if (r < FF + ORD) {
            w.x = kern[r * 1024 + n];
            w.y = kern[r * 1024 + 256 + n];
            w.z = kern[r * 1024 + 512 + n];
            w.w = kern[r * 1024 + 768 + n];
        } else {
            int rr = r - (FF + ORD);
            w.x = rec[rr * 1024 + n];
            w.y = rec[rr * 1024 + 256 + n];
            w.z = rec[rr * 1024 + 512 + n];
            w.w = rec[rr * 1024 + 768 + n];
        }
        g_Wp[idx] = w;
    }
    for (int n = i; n < KK; n += stride) {
        float4 b;
        b.x = bias[n];
        b.y = bias[256 + n];
        b.z = bias[512 + n];
        b.w = bias[768 + n];
        g_biasp[n] = b;
    }
}

// ---------------- one LSTM timestep: fused GEMM + gates ---------------------
// grid: (B/MT = 128, K/NT = 4), block: 256 threads
// thread micro-tile: 4 rows x 4 hidden units x 4 gates
__global__ void __launch_bounds__(NTHREADS)
lstm_step(const float* __restrict__ x, int t, int parity) {
    __shared__ float  As[KC][MT + 1];   // +1 pad kills STS bank conflicts
    __shared__ float4 Ws[KC][NT];

    const int tid = threadIdx.x;
    const int tx  = tid & 15;           // hidden-unit group (strided by 16)
    const int ty  = tid >> 4;           // row group (strided by 16)
    const int mrow0 = blockIdx.x * MT;
    const int ncol0 = blockIdx.y * NT;

    const float* __restrict__ hprev = g_hbuf + (size_t)parity * BB * KK;
    float*       __restrict__ hnext = g_hbuf + (size_t)(parity ^ 1) * BB * KK;

    unsigned long long acc[4][4][2];    // [row][unit][gate-pair], each = 2 f32
    #pragma unroll
    for (int r = 0; r < 4; r++)
        #pragma unroll
        for (int j = 0; j < 4; j++) {
            acc[r][j][0] = 0ull;
            acc[r][j][1] = 0ull;
        }

    for (int kb = 0; kb < RTOT / KC; kb++) {
        // ---- stage A tile: 16 x 64 (k-major for broadcast) ----
        #pragma unroll
        for (int i = 0; i < 4; i++) {
            int s  = tid + i * NTHREADS;
            int kk = s & 15;
            int m  = s >> 4;
            int row = mrow0 + m;
            float v;
            if (kb < 4)        v = x[(size_t)row * (TT * FF) + t * FF + (kb * KC + kk)];
            else if (kb == 4)  v = g_yp[row * ORD + kk];
            else               v = hprev[(size_t)row * KK + ((kb - 5) * KC + kk)];
            As[kk][m] = v;
        }
        // ---- stage W tile: 16 x 64 float4 ----
        #pragma unroll
        for (int i = 0; i < 4; i++) {
            int s  = tid + i * NTHREADS;
            int kk = s >> 6;
            int n  = s & 63;
            Ws[kk][n] = g_Wp[(kb * KC + kk) * KK + ncol0 + n];
        }
        __syncthreads();

        // ---- compute ----
        #pragma unroll
        for (int kk = 0; kk < KC; kk++) {
            unsigned long long a2[4];
            #pragma unroll
            for (int r = 0; r < 4; r++)
                a2[r] = bcast2(As[kk][ty + 16 * r]);
            #pragma unroll
            for (int j = 0; j < 4; j++) {
                const ulonglong2 wv =
                    *reinterpret_cast<const ulonglong2*>(&Ws[kk][tx + 16 * j]);
                #pragma unroll
                for (int r = 0; r < 4; r++) {
                    fma2(acc[r][j][0], a2[r], wv.x);   // gates (i, f)
                    fma2(acc[r][j][1], a2[r], wv.y);   // gates (g, o)
                }
            }
        }
        __syncthreads();
    }

    // ---- epilogue: bias + gates + state update ----
    #pragma unroll
    for (int r = 0; r < 4; r++) {
        const int row = mrow0 + ty + 16 * r;
        #pragma unroll
        for (int j = 0; j < 4; j++) {
            const int n = ncol0 + tx + 16 * j;
            const float4 bp = g_biasp[n];
            float2 zif = unpack2(acc[r][j][0]);
            float2 zgo = unpack2(acc[r][j][1]);
            float gi = sigmoidf_(zif.x + bp.x);
            float gf = sigmoidf_(zif.y + bp.y);
            float gg = tanhf(zgo.x + bp.z);
            float go = sigmoidf_(zgo.y + bp.w);
            const size_t off = (size_t)row * KK + n;
            float cnew = gf * g_c[off] + gi * gg;
            float hnew = go * tanhf(cnew);
            g_c[off]   = cnew;
            hnext[off] = hnew;
        }
    }
}

// ---------------- finalize: pred = h_new @ dense_w + b; shift window --------
// one warp per batch row; deterministic (no atomics)
__global__ void finalize_kernel(float* __restrict__ out,
                                const float* __restrict__ dw,
                                const float* __restrict__ db,
                                int t, int parity) {
    const int warp = (blockIdx.x * blockDim.x + threadIdx.x) >> 5;
    const int lane = threadIdx.x & 31;
    if (warp >= BB) return;
    const float* h = g_hbuf + (size_t)(parity ^ 1) * BB * KK + (size_t)warp * KK;
    float s = 0.0f;
    #pragma unroll
    for (int i = 0; i < KK / 32; i++)
        s += h[lane + 32 * i] * dw[lane + 32 * i];
    #pragma unroll
    for (int off = 16; off >= 1; off >>= 1)
        s += __shfl_xor_sync(0xffffffffu, s, off);
    const float p = s + db[0];        // all lanes hold p

    float* yp = &g_yp[warp * ORD];
    float ypv = (lane < ORD - 1) ? yp[lane] : 0.0f;
    float up  = __shfl_up_sync(0xffffffffu, ypv, 1);
    if (lane == 0) {
        out[(size_t)warp * TT + t] = p;
        yp[0] = p;
    } else if (lane <= ORD - 1) {
        yp[lane] = up;                // yp[l] = old yp[l-1]
    }
}

// ---------------- launch ----------------------------------------------------
extern "C" void kernel_launch(void* const* d_in, const int* in_sizes, int n_in,
                              void* d_out, int out_size) {
    const float* x    = (const float*)d_in[0];  // [8192, 64, 64]
    const float* y0   = (const float*)d_in[1];  // [8192, 16]
    const float* kern = (const float*)d_in[2];  // [80, 1024]
    const float* rec  = (const float*)d_in[3];  // [256, 1024]
    const float* bias = (const float*)d_in[4];  // [1024]
    const float* dw   = (const float*)d_in[5];  // [256, 1]
    const float* db   = (const float*)d_in[6];  // [1]
    float* out = (float*)d_out;                 // [8192, 64, 1]

    init_kernel<<<2048, 256>>>(y0);
    repack_kernel<<<512, 256>>>(kern, rec, bias);

    dim3 grid(BB / MT, KK / NT);    // (128, 4)
    for (int t = 0; t < TT; t++) {
        lstm_step<<<grid, NTHREADS>>>(x, t, t & 1);
        finalize_kernel<<<BB * 32 / 256, 256>>>(out, dw, db, t, t & 1);
    }
}

// round 6
// speedup vs baseline: 1.3151x; 1.3151x over previous
#include <cuda_runtime.h>
#include <cuda_bf16.h>
#include <cstdint>

#define BB   8192
#define TT   64
#define FF   64
#define ORD  16
#define KK   256            // hidden units
#define RTOT 336            // F + ORD + K
#define NCH  21             // 336/16 k-chunks
#define MT   128            // rows per CTA
#define NT   256            // z-cols per CTA (64 units * 4 gates)
#define NTH  512

// smem: staged tiles, rows padded to 48B for conflict-free ldmatrix
#define ROWB   48
#define OFF_AH 0
#define OFF_AL (128 * ROWB)            // 6144
#define OFF_WH (2 * 128 * ROWB)        // 12288
#define OFF_WL (OFF_WH + 256 * ROWB)   // 24576
#define BUFSZ  (OFF_WL + 256 * ROWB)   // 36864
#define OFF_PART (2 * BUFSZ)           // 73728, 128x4 floats
#define SMEM_TOTAL (OFF_PART + 128 * 4 * 4 + 256)

// ---------------- persistent device state ----------------
__device__ __align__(16) __nv_bfloat16 g_Xh[(size_t)BB * TT * FF];
__device__ __align__(16) __nv_bfloat16 g_Xl[(size_t)BB * TT * FF];
__device__ __align__(16) __nv_bfloat16 g_Hh[2][(size_t)BB * KK];
__device__ __align__(16) __nv_bfloat16 g_Hl[2][(size_t)BB * KK];
__device__ __align__(16) float g_c[(size_t)BB * KK];
__device__ __align__(16) __nv_bfloat16 g_YPh[BB * ORD];
__device__ __align__(16) __nv_bfloat16 g_YPl[BB * ORD];
__device__ __align__(16) __nv_bfloat16 g_Wth[1024 * RTOT];   // [n'=4u+g][k]
__device__ __align__(16) __nv_bfloat16 g_Wtl[1024 * RTOT];
__device__ float4 g_biasp[KK];
__device__ float  g_part[4 * BB];      // per-col-CTA partial dense dots

// ---------------- helpers ----------------
__device__ __forceinline__ uint32_t smem_u32(const void* p) {
    uint32_t a;
    asm("{ .reg .u64 t; cvta.to.shared.u64 t, %1; cvt.u32.u64 %0, t; }" : "=r"(a) : "l"(p));
    return a;
}
__device__ __forceinline__ void cpa16(uint32_t dst, const void* src) {
    asm volatile("cp.async.cg.shared.global [%0], [%1], 16;" :: "r"(dst), "l"(src) : "memory");
}
__device__ __forceinline__ void ldsm4(uint32_t (&r)[4], uint32_t a) {
    asm volatile("ldmatrix.sync.aligned.m8n8.x4.shared.b16 {%0,%1,%2,%3}, [%4];"
                 : "=r"(r[0]), "=r"(r[1]), "=r"(r[2]), "=r"(r[3]) : "r"(a));
}
__device__ __forceinline__ void mma16816(float (&d)[4], const uint32_t (&a)[4],
                                         uint32_t b0, uint32_t b1) {
    asm volatile("mma.sync.aligned.m16n8k16.row.col.f32.bf16.bf16.f32 "
                 "{%0,%1,%2,%3}, {%4,%5,%6,%7}, {%8,%9}, {%0,%1,%2,%3};"
                 : "+f"(d[0]), "+f"(d[1]), "+f"(d[2]), "+f"(d[3])
                 : "r"(a[0]), "r"(a[1]), "r"(a[2]), "r"(a[3]), "r"(b0), "r"(b1));
}
__device__ __forceinline__ float sigm(float x) { return 1.0f / (1.0f + __expf(-x)); }
__device__ __forceinline__ float tanh_(float x) {
    float e = __expf(2.0f * x);
    return 1.0f - 2.0f / (e + 1.0f);
}
__device__ __forceinline__ void split_bf16(float v, __nv_bfloat16& hi, __nv_bfloat16& lo) {
    hi = __float2bfloat16(v);
    lo = __float2bfloat16(v - __bfloat162float(hi));
}

// ---------------- setup kernels ----------------
__global__ void conv_x_kernel(const float* __restrict__ x) {
    size_t n = (size_t)BB * TT * FF;
    for (size_t i = (size_t)blockIdx.x * blockDim.x + threadIdx.x; i < n;
         i += (size_t)gridDim.x * blockDim.x) {
        __nv_bfloat16 h, l;
        split_bf16(x[i], h, l);
        g_Xh[i] = h; g_Xl[i] = l;
    }
}
__global__ void init_state_kernel(const float* __restrict__ y0) {
    int i = blockIdx.x * blockDim.x + threadIdx.x;
    int st = gridDim.x * blockDim.x;
    __nv_bfloat16 z = __float2bfloat16(0.0f);
    for (size_t s = i; s < (size_t)BB * KK; s += st) {
        g_c[s] = 0.0f;
        g_Hh[0][s] = z; g_Hl[0][s] = z;
        g_Hh[1][s] = z; g_Hl[1][s] = z;
    }
    for (int s = i; s < BB * ORD; s += st) {
        __nv_bfloat16 h, l;
        split_bf16(y0[s], h, l);
        g_YPh[s] = h; g_YPl[s] = l;
    }
}
__global__ void repack_w_kernel(const float* __restrict__ kern,  // [80,1024]
                                const float* __restrict__ rec,   // [256,1024]
                                const float* __restrict__ bias) {
    int i = blockIdx.x * blockDim.x + threadIdx.x;
    int st = gridDim.x * blockDim.x;
    for (int idx = i; idx < 1024 * RTOT; idx += st) {
        int np = idx / RTOT;
        int k  = idx - np * RTOT;
        int u = np >> 2, g = np & 3;
        int col = g * 256 + u;                  // Keras gate order i,f,c,o
        float v = (k < FF + ORD) ? kern[k * 1024 + col] : rec[(k - 80) * 1024 + col];
        __nv_bfloat16 h, l;
        split_bf16(v, h, l);
        g_Wth[idx] = h; g_Wtl[idx] = l;
    }
    for (int u = i; u < KK; u += st) {
        float4 b;
        b.x = bias[u]; b.y = bias[256 + u]; b.z = bias[512 + u]; b.w = bias[768 + u];
        g_biasp[u] = b;
    }
}

// ---------------- fused timestep: HMMA GEMM + gates + partial dense ---------
// grid (64, 4), 512 threads. Warp tile 32 rows x 64 cols. acc fp32.
__global__ void __launch_bounds__(NTH, 1)
lstm_step(int t, int par, const float* __restrict__ dw) {
    extern __shared__ __align__(16) char sm[];
    const uint32_t sb = smem_u32(sm);
    const int tid  = threadIdx.x;
    const int wid  = tid >> 5;
    const int lane = tid & 31;
    const int g8   = lane >> 2;      // groupID (row within m16 half)
    const int tid4 = lane & 3;
    const int warpM = wid & 3;       // 4 row groups * 32 rows
    const int warpN = wid >> 2;      // 4 col groups * 64 cols
    const int mrow0 = blockIdx.x * MT;
    const int ncol0 = blockIdx.y * NT;

    const __nv_bfloat16* __restrict__ Hh = g_Hh[par];
    const __nv_bfloat16* __restrict__ Hl = g_Hl[par];

    // --- staging lambda: one k16 chunk into buffer b ---
    auto stage = [&](int kc, int b) {
        uint32_t bufb = sb + b * BUFSZ;
        // A: 128 rows x {hi,lo} x {k8 halves} = 512 jobs
        {
            int row  = tid >> 2;
            int half = tid & 1;
            int hilo = (tid >> 1) & 1;
            int kg   = kc * 16 + half * 8;
            int grow = mrow0 + row;
            const __nv_bfloat16* src;
            if (kg < 64)
                src = (hilo ? g_Xl : g_Xh) + (size_t)grow * (TT * FF) + t * FF + kg;
            else if (kg < 80)
                src = (hilo ? g_YPl : g_YPh) + grow * ORD + (kg - 64);
            else
                src = (hilo ? Hl : Hh) + (size_t)grow * KK + (kg - 80);
            cpa16(bufb + (hilo ? OFF_AL : OFF_AH) + row * ROWB + half * 16, src);
        }
        // W: 256 n-rows x {hi,lo} x {halves} = 1024 jobs, 2 per thread
        #pragma unroll
        for (int j = 0; j < 2; j++) {
            int idx  = tid + j * NTH;
            int n    = idx >> 2;
            int half = idx & 1;
            int hilo = (idx >> 1) & 1;
            const __nv_bfloat16* src =
                (hilo ? g_Wtl : g_Wth) + (size_t)(ncol0 + n) * RTOT + kc * 16 + half * 8;
            cpa16(bufb + (hilo ? OFF_WL : OFF_WH) + n * ROWB + half * 16, src);
        }
        asm volatile("cp.async.commit_group;" ::: "memory");
    };

    float acc[2][8][4];
    #pragma unroll
    for (int mi = 0; mi < 2; mi++)
        #pragma unroll
        for (int nj = 0; nj < 8; nj++)
            #pragma unroll
            for (int q = 0; q < 4; q++) acc[mi][nj][q] = 0.0f;

    stage(0, 0);
    const int lrow = lane & 15;            // ldmatrix row-in-tile
    const int lcol16 = (lane >> 4) * 16;   // ldmatrix 16B column half

    for (int kc = 0; kc < NCH; kc++) {
        if (kc + 1 < NCH) {
            stage(kc + 1, (kc + 1) & 1);
            asm volatile("cp.async.wait_group 1;" ::: "memory");
        } else {
            asm volatile("cp.async.wait_group 0;" ::: "memory");
        }
        __syncthreads();

        const uint32_t bufb = sb + (kc & 1) * BUFSZ;
        uint32_t ah[2][4], al[2][4];
        #pragma unroll
        for (int mi = 0; mi < 2; mi++) {
            uint32_t ra = (warpM * 32 + mi * 16 + lrow) * ROWB + lcol16;
            ldsm4(ah[mi], bufb + OFF_AH + ra);
            ldsm4(al[mi], bufb + OFF_AL + ra);
        }
        #pragma unroll
        for (int nb = 0; nb < 4; nb++) {
            uint32_t rw = (warpN * 64 + nb * 16 + lrow) * ROWB + lcol16;
            uint32_t wh[4], wl[4];
            // W stored [n][k]: mma .col layout == row-major n x k, so NON-trans ldmatrix
            ldsm4(wh, bufb + OFF_WH + rw);
            ldsm4(wl, bufb + OFF_WL + rw);
            #pragma unroll
            for (int mi = 0; mi < 2; mi++) {
                mma16816(acc[mi][2 * nb + 0], ah[mi], wh[0], wh[2]);
                mma16816(acc[mi][2 * nb + 1], ah[mi], wh[1], wh[3]);
                mma16816(acc[mi][2 * nb + 0], al[mi], wh[0], wh[2]);
                mma16816(acc[mi][2 * nb + 1], al[mi], wh[1], wh[3]);
                mma16816(acc[mi][2 * nb + 0], ah[mi], wl[0], wl[2]);
                mma16816(acc[mi][2 * nb + 1], ah[mi], wl[1], wl[3]);
            }
        }
        __syncthreads();
    }

    // ---- epilogue: gates, state update, partial dense dot ----
    __nv_bfloat16* __restrict__ Hho = g_Hh[par ^ 1];
    __nv_bfloat16* __restrict__ Hlo = g_Hl[par ^ 1];
    float rd[4] = {0.0f, 0.0f, 0.0f, 0.0f};
    const bool evenlane = ((tid4 & 1) == 0);

    #pragma unroll
    for (int mi = 0; mi < 2; mi++) {
        #pragma unroll
        for (int nj = 0; nj < 8; nj++) {
            float c0 = acc[mi][nj][0], c1 = acc[mi][nj][1];
            float c2 = acc[mi][nj][2], c3 = acc[mi][nj][3];
            float o0 = __shfl_xor_sync(0xffffffffu, c0, 1);
            float o1 = __shfl_xor_sync(0xffffffffu, c1, 1);
            float o2 = __shfl_xor_sync(0xffffffffu, c2, 1);
            float o3 = __shfl_xor_sync(0xffffffffu, c3, 1);
            if (evenlane) {
                const int u = ((ncol0 + warpN * 64 + nj * 8) >> 2) + (tid4 >> 1);
                const float4 bp = g_biasp[u];
                const float dwu = dw[u];
                const int r0 = mrow0 + warpM * 32 + mi * 16 + g8;
                #pragma unroll
                for (int rr = 0; rr < 2; rr++) {
                    const float zi = rr ? c2 : c0;
                    const float zf = rr ? c3 : c1;
                    const float zg = rr ? o2 : o0;
                    const float zo = rr ? o3 : o1;
                    const int row = r0 + rr * 8;
                    const size_t off = (size_t)row * KK + u;
                    float gi = sigm(zi + bp.x);
                    float gf = sigm(zf + bp.y);
                    float gg = tanh_(zg + bp.z);
                    float go = sigm(zo + bp.w);
                    float cn = gf * g_c[off] + gi * gg;
                    g_c[off] = cn;
                    float hn = go * tanh_(cn);
                    __nv_bfloat16 hh, hl;
                    split_bf16(hn, hh, hl);
                    Hho[off] = hh;
                    Hlo[off] = hl;
                    rd[mi * 2 + rr] += hn * dwu;
                }
            }
        }
    }
    // combine tid4 0<->2
    #pragma unroll
    for (int q = 0; q < 4; q++)
        rd[q] += __shfl_xor_sync(0xffffffffu, rd[q], 2);

    float* part = (float*)(sm + OFF_PART);   // [128][4]
    if (tid4 == 0) {
        #pragma unroll
        for (int mi = 0; mi < 2; mi++)
            #pragma unroll
            for (int rr = 0; rr < 2; rr++)
                part[(warpM * 32 + mi * 16 + g8 + rr * 8) * 4 + warpN] = rd[mi * 2 + rr];
    }
    __syncthreads();
    if (tid < 128) {
        float s = part[tid * 4 + 0] + part[tid * 4 + 1] +
                  part[tid * 4 + 2] + part[tid * 4 + 3];
        g_part[blockIdx.y * BB + mrow0 + tid] = s;
    }
}

// ---------------- finalize: sum partials, emit pred, shift window -----------
__global__ void finalize_kernel(float* __restrict__ out,
                                const float* __restrict__ db, int t) {
    const int row = blockIdx.x * blockDim.x + threadIdx.x;
    if (row >= BB) return;
    float p = g_part[row] + g_part[BB + row] + g_part[2 * BB + row] +
              g_part[3 * BB + row] + db[0];
    out[(size_t)row * TT + t] = p;

    __nv_bfloat16* yph = g_YPh + row * ORD;
    __nv_bfloat16* ypl = g_YPl + row * ORD;
    __nv_bfloat16 th[ORD], tl[ORD];
    #pragma unroll
    for (int i = 0; i < ORD; i++) { th[i] = yph[i]; tl[i] = ypl[i]; }
    #pragma unroll
    for (int i = ORD - 1; i >= 1; i--) { yph[i] = th[i - 1]; ypl[i] = tl[i - 1]; }
    __nv_bfloat16 ph, pl;
    split_bf16(p, ph, pl);
    yph[0] = ph; ypl[0] = pl;
}

// ---------------- launch ----------------
extern "C" void kernel_launch(void* const* d_in, const int* in_sizes, int n_in,
                              void* d_out, int out_size) {
    const float* x    = (const float*)d_in[0];
    const float* y0   = (const float*)d_in[1];
    const float* kern = (const float*)d_in[2];
    const float* rec  = (const float*)d_in[3];
    const float* bias = (const float*)d_in[4];
    const float* dw   = (const float*)d_in[5];
    const float* db   = (const float*)d_in[6];
    float* out = (float*)d_out;

    cudaFuncSetAttribute(lstm_step,
                         cudaFuncAttributeMaxDynamicSharedMemorySize, SMEM_TOTAL);

    conv_x_kernel<<<2048, 256>>>(x);
    init_state_kernel<<<1024, 256>>>(y0);
    repack_w_kernel<<<1024, 256>>>(kern, rec, bias);

    dim3 grid(BB / MT, 4);   // (64, 4)
    for (int t = 0; t < TT; t++) {
        lstm_step<<<grid, NTH, SMEM_TOTAL>>>(t, t & 1, dw);
        finalize_kernel<<<BB / 256, 256>>>(out, db, t);
    }
}